// round 11
// baseline (speedup 1.0000x reference)
#include <cuda_runtime.h>
#include <cstdint>

#define PI_F 3.14159265358979323846f

// Packed 4-bit species table (up to 131072 atoms)
__device__ __align__(16) unsigned g_pk[16384];

// ---------------------------------------------------------------------------
// Prep kernel: zero aev AND pack atomic_numbers into 4-bit nibbles.
// ---------------------------------------------------------------------------
__global__ void ani_prep_kernel(const int* __restrict__ an, int N, int PKW,
                                float4* __restrict__ aevv, long long aev_v4)
{
    long long t = (long long)blockIdx.x * blockDim.x + threadIdx.x;
    const float4 z = make_float4(0.f, 0.f, 0.f, 0.f);
    for (long long v = t; v < aev_v4; v += (long long)gridDim.x * blockDim.x)
        aevv[v] = z;
    if (t < PKW) {
        int base = (int)t << 3;
        unsigned v = 0;
#pragma unroll
        for (int k = 0; k < 8; k++) {
            int a = base + k;
            unsigned s = (a < N) ? (unsigned)an[a] : 0u;
            v |= (s & 15u) << (k * 4);
        }
        g_pk[t] = v;
    }
}

// ---------------------------------------------------------------------------
// Main kernel, single wave, per-block roles:
//   b <  RB : radial-persistent  (25KB smem species table, grid-stride pairs,
//             scattered RED.128 atomics -- the irreducible LSU load)
//   b >= RB : angular-persistent; output flushed via cp.async.bulk
//             (TMA bulk store) so the 205MB stream costs ZERO L1tex wavefronts.
// smem union 32.8KB -> 6 blocks/SM.
// ---------------------------------------------------------------------------
__global__ __launch_bounds__(256, 6)
void ani_main_kernel(const float* __restrict__ r_ij,
                     const int*   __restrict__ pidx,
                     const int*   __restrict__ an,
                     const float* __restrict__ vec12,
                     float*       __restrict__ aev,
                     float*       __restrict__ ang,
                     int P, int T, int PKB, int RB, int G)
{
    __shared__ __align__(128) unsigned char smraw[33024];

    const int tid = threadIdx.x;
    const int b   = blockIdx.x;

    if (b < RB) {
        // ===================== RADIAL (persistent) ========================
        unsigned* spk = reinterpret_cast<unsigned*>(smraw);
        unsigned long long* mb = reinterpret_cast<unsigned long long*>(smraw + 25088);
        const bool use_table = (PKB > 0);
        uint32_t mbar_a = (uint32_t)__cvta_generic_to_shared(mb);

        if (use_table) {
            if (tid == 0) {
                asm volatile("mbarrier.init.shared.b64 [%0], 1;" :: "r"(mbar_a) : "memory");
                asm volatile("fence.proxy.async.shared::cta;" ::: "memory");
            }
            __syncthreads();
            if (tid == 0) {
                uint32_t dst = (uint32_t)__cvta_generic_to_shared(spk);
                asm volatile("mbarrier.arrive.expect_tx.shared.b64 _, [%0], %1;"
                             :: "r"(mbar_a), "r"((unsigned)PKB) : "memory");
                asm volatile("cp.async.bulk.shared::cluster.global.mbarrier::complete_tx::bytes "
                             "[%0], [%1], %2, [%3];"
                             :: "r"(dst), "l"((const void*)g_pk), "r"((unsigned)PKB), "r"(mbar_a)
                             : "memory");
            }
            unsigned done;
            do {
                asm volatile("{\n\t.reg .pred p;\n\t"
                             "mbarrier.try_wait.parity.shared.b64 p, [%1], 0;\n\t"
                             "selp.b32 %0, 1, 0, p;\n\t}"
                             : "=r"(done) : "r"(mbar_a) : "memory");
            } while (!done);
        }

        const long long stride = (long long)RB * 256;
        for (long long base = (long long)b * 256; base < P; base += stride) {
            long long p = base + tid;
            if (p < P) {
                float d = __ldcs(r_ij + p);
                int   i = pidx[p];
                int   j = pidx[P + p];
                int si, sj;
                if (use_table) {
                    si = (spk[i >> 3] >> ((i & 7) * 4)) & 7;
                    sj = (spk[j >> 3] >> ((j & 7) * 4)) & 7;
                } else {
                    si = an[i];
                    sj = an[j];
                }
                float fc = (d <= 5.1f) ? (0.5f * __cosf((PI_F / 5.1f) * d) + 0.5f) : 0.0f;
                float f[8];
#pragma unroll
                for (int k = 0; k < 8; k++) {
                    float dd = d - (0.8f + 0.5375f * (float)k);   // ShfR[k]
                    f[k] = 0.25f * __expf(-19.7f * dd * dd) * fc;
                }
                float4 lo = make_float4(f[0], f[1], f[2], f[3]);
                float4 hi = make_float4(f[4], f[5], f[6], f[7]);
                float4* rA = reinterpret_cast<float4*>(aev + (long long)(i * 7 + sj) * 8);
                float4* rB = reinterpret_cast<float4*>(aev + (long long)(j * 7 + si) * 8);
                atomicAdd(rA,     lo);
                atomicAdd(rA + 1, hi);
                atomicAdd(rB,     lo);
                atomicAdd(rB + 1, hi);
            }
        }
    } else {
        // ==================== ANGULAR (persistent, TMA flush) =============
        float* buf0 = reinterpret_cast<float*>(smraw);            // 16384B
        float* buf1 = reinterpret_cast<float*>(smraw + 16384);    // 16384B

        const int nA = G - RB;
        const long long nTiles = ((long long)T + 255) / 256;
        const long long limit  = (long long)T * 32;

        const float CZ[4] = { 0.9238795325f,  0.3826834324f, -0.3826834324f, -0.9238795325f };
        const float SZ[4] = { 0.3826834324f,  0.9238795325f,  0.9238795325f,  0.3826834324f };

        for (long long tile = b - RB; tile < nTiles; tile += nA) {
            const long long t = tile * 256 + tid;
            const bool vt = (t < T);

            float cost = 0.f, sint = 0.f, fc2x = 0.f;
            float frad[8];
#pragma unroll
            for (int a = 0; a < 8; a++) frad[a] = 0.f;

            if (vt) {
                const float* v1 = vec12 + 3LL * t;
                const float* v2 = vec12 + 3LL * T + 3LL * t;
                float x1 = __ldcs(v1 + 0), y1 = __ldcs(v1 + 1), z1 = __ldcs(v1 + 2);
                float x2 = __ldcs(v2 + 0), y2 = __ldcs(v2 + 1), z2 = __ldcs(v2 + 2);

                float d11 = fmaf(x1, x1, fmaf(y1, y1, z1 * z1));
                float d22 = fmaf(x2, x2, fmaf(y2, y2, z2 * z2));
                float d12 = fmaf(x1, x2, fmaf(y1, y2, z1 * z2));

                float rs1 = rsqrtf(d11);
                float rs2 = rsqrtf(d22);
                float d1  = d11 * rs1;
                float d2  = d22 * rs2;

                cost = 0.95f * d12 * rs1 * rs2;                 // |cost| <= 0.95
                sint = sqrtf(fmaxf(1.0f - cost * cost, 0.0f));  // theta in [0,pi]

                float fc1 = (d1 <= 3.5f) ? (0.5f * __cosf((PI_F / 3.5f) * d1) + 0.5f) : 0.0f;
                float fc2 = (d2 <= 3.5f) ? (0.5f * __cosf((PI_F / 3.5f) * d2) + 0.5f) : 0.0f;
                fc2x = 2.0f * fc1 * fc2;

                float u = 0.5f * (d1 + d2);
#pragma unroll
                for (int a = 0; a < 8; a++) {
                    float dd = u - (0.8f + 0.3375f * (float)a);   // ShfA[a]
                    frad[a] = __expf(-12.5f * dd * dd);
                }
            }

            // fang per angle section (after x fc2x)
            float fang[4];
#pragma unroll
            for (int z = 0; z < 4; z++) {
                float xz = 0.5f * (1.0f + cost * CZ[z] + sint * SZ[z]);   // in [0,1]
                fang[z] = ((xz > 0.0f) ? __powf(xz, 14.1f) : 0.0f) * fc2x;
            }

            // two passes: 128 rows each, staged contiguously with column
            // rotation (chunk (m+r)&7) -> conflict-free STS.128, then bulk-store.
#pragma unroll
            for (int pass = 0; pass < 2; pass++) {
                float* buf = pass ? buf1 : buf0;

                // make sure the bulk engine finished READING this buffer
                if (tid == 0)
                    asm volatile("cp.async.bulk.wait_group.read 1;" ::: "memory");
                __syncthreads();

                if ((tid >> 7) == pass) {
                    int r = tid & 127;
#pragma unroll
                    for (int m = 0; m < 8; m++) {
                        int c = (m + r) & 7;          // rotated chunk index
                        int z = c >> 1;
                        int a0 = (c & 1) * 4;
                        float fz = fang[z];
                        float4 v = make_float4(fz * frad[a0],     fz * frad[a0 + 1],
                                               fz * frad[a0 + 2], fz * frad[a0 + 3]);
                        *reinterpret_cast<float4*>(&buf[r * 32 + c * 4]) = v;
                    }
                }
                __syncthreads();

                const long long base = (tile * 256 + pass * 128) * 32;   // floats
                if (base >= limit) continue;

                if (base + 4096 <= limit) {
                    // full 16KB tile: TMA bulk store, zero LSU wavefronts
                    if (tid == 0) {
                        asm volatile("fence.proxy.async.shared::cta;" ::: "memory");
                        uint32_t src = (uint32_t)__cvta_generic_to_shared(buf);
                        asm volatile("cp.async.bulk.global.shared::cta.bulk_group [%0], [%1], %2;"
                                     :: "l"(ang + base), "r"(src), "r"(16384u) : "memory");
                        asm volatile("cp.async.bulk.commit_group;" ::: "memory");
                    }
                } else {
                    // partial tail tile: fallback coalesced stores
                    float4* outv = reinterpret_cast<float4*>(ang + base);
#pragma unroll
                    for (int it = 0; it < 4; it++) {
                        int jj = tid + it * 256;
                        if (base + (long long)jj * 4 < limit)
                            __stcs(&outv[jj],
                                   *reinterpret_cast<const float4*>(&buf[jj * 4]));
                    }
                }
            }
        }
        // drain outstanding bulk stores before block exit
        if (tid == 0)
            asm volatile("cp.async.bulk.wait_group.read 0;" ::: "memory");
    }
}

// ---------------------------------------------------------------------------
// Inputs (metadata order): r_ij f32[P], pair_indices i32[2,P],
// atomic_numbers i32[N_ATOMS], vec12 f32[2,T,3].
// Output: aev f32[N_ATOMS*7, 8] followed by ang f32[T, 32].
// ---------------------------------------------------------------------------
extern "C" void kernel_launch(void* const* d_in, const int* in_sizes, int n_in,
                              void* d_out, int out_size)
{
    const float* r_ij  = (const float*)d_in[0];
    const int*   pidx  = (const int*)  d_in[1];
    const int*   an    = (const int*)  d_in[2];
    const float* vec12 = (const float*)d_in[3];

    const int P = in_sizes[0];
    const int T = in_sizes[3] / 6;
    const int N = in_sizes[2];
    const long long aev_elems = (long long)N * 7 * 8;

    float* aev = (float*)d_out;
    float* ang = aev + aev_elems;

    const int PKW = (N + 7) / 8;
    int PKB = ((PKW * 4) + 15) & ~15;
    if (PKB > 25088) PKB = 0;

    static int nsm = 0;
    if (nsm == 0) {
        if (cudaDeviceGetAttribute(&nsm, cudaDevAttrMultiProcessorCount, 0) != cudaSuccess
            || nsm <= 0)
            nsm = 148;
    }

    int RB = 2 * nsm;                 // radial blocks (~2 per SM)
    int G  = 6 * nsm;                 // one full wave at 6 blocks/SM
    const int RTmax = (P + 255) / 256;
    if (RB > RTmax) RB = (RTmax > 0) ? RTmax : 1;
    if (G <= RB) G = RB + 1;

    // zero aev + pack species
    ani_prep_kernel<<<2048, 256>>>(an, N, (PKB > 0) ? (PKB / 4) : 0,
                                   (float4*)aev, aev_elems / 4);

    ani_main_kernel<<<G, 256>>>(r_ij, pidx, an, vec12, aev, ang, P, T, PKB, RB, G);
}

// round 12
// speedup vs baseline: 1.4426x; 1.4426x over previous
#include <cuda_runtime.h>
#include <cstdint>

#define PI_F 3.14159265358979323846f

// Packed 4-bit species table (up to 131072 atoms)
__device__ __align__(16) unsigned g_pk[16384];

// ---------------------------------------------------------------------------
// Prep kernel: zero aev AND pack atomic_numbers into 4-bit nibbles.
// ---------------------------------------------------------------------------
__global__ void ani_prep_kernel(const int* __restrict__ an, int N, int PKW,
                                float4* __restrict__ aevv, long long aev_v4)
{
    long long t = (long long)blockIdx.x * blockDim.x + threadIdx.x;
    const float4 z = make_float4(0.f, 0.f, 0.f, 0.f);
    for (long long v = t; v < aev_v4; v += (long long)gridDim.x * blockDim.x)
        aevv[v] = z;
    if (t < PKW) {
        int base = (int)t << 3;
        unsigned v = 0;
#pragma unroll
        for (int k = 0; k < 8; k++) {
            int a = base + k;
            unsigned s = (a < N) ? (unsigned)an[a] : 0u;
            v |= (s & 15u) << (k * 4);
        }
        g_pk[t] = v;
    }
}

__device__ __forceinline__ float4 radial_half4(float d, float base_k, float fc)
{
    float a0 = d - base_k;
    float a1 = d - (base_k + 0.5375f);
    float a2 = d - (base_k + 1.075f);
    float a3 = d - (base_k + 1.6125f);
    return make_float4(0.25f * __expf(-19.7f * a0 * a0) * fc,
                       0.25f * __expf(-19.7f * a1 * a1) * fc,
                       0.25f * __expf(-19.7f * a2 * a2) * fc,
                       0.25f * __expf(-19.7f * a3 * a3) * fc);
}

// ---------------------------------------------------------------------------
// Fused kernel (R8 structure), 512 threads/block, 3 blocks/SM:
//   smem = 25KB species table (cp.async.bulk) + 18.4KB stage (128 rows).
//   Radial: Gaussian-window culling -- only the significant aligned float4
//   half/halves (|d - mu_k| < 0.85A) are computed and atomically added.
//   ~65-70% of pairs touch ONE half -> ~32% fewer LTS atomic slots.
// ---------------------------------------------------------------------------
__global__ __launch_bounds__(512, 3)
void ani_fused_kernel(const float* __restrict__ r_ij,
                      const int*   __restrict__ pidx,
                      const int*   __restrict__ an,
                      const float* __restrict__ vec12,
                      float*       __restrict__ aev,
                      float*       __restrict__ ang,
                      int P, int T, int PKB /*bulk bytes, 0 = no table*/)
{
    __shared__ __align__(128) unsigned spk[6272];      // 25088B table
    __shared__ __align__(16)  float    sf[128 * 36];   // 18432B stage (128 rows)
    __shared__ __align__(8)   unsigned long long mbar;

    const int tid = threadIdx.x;
    const int b   = blockIdx.x;
    const bool use_table = (PKB > 0);

    uint32_t mbar_a = (uint32_t)__cvta_generic_to_shared(&mbar);

    if (use_table) {
        if (tid == 0) {
            asm volatile("mbarrier.init.shared.b64 [%0], 1;" :: "r"(mbar_a) : "memory");
            asm volatile("fence.proxy.async.shared::cta;" ::: "memory");
        }
        __syncthreads();
        if (tid == 0) {
            uint32_t dst = (uint32_t)__cvta_generic_to_shared(spk);
            asm volatile("mbarrier.arrive.expect_tx.shared.b64 _, [%0], %1;"
                         :: "r"(mbar_a), "r"((unsigned)PKB) : "memory");
            asm volatile("cp.async.bulk.shared::cluster.global.mbarrier::complete_tx::bytes "
                         "[%0], [%1], %2, [%3];"
                         :: "r"(dst), "l"((const void*)g_pk), "r"((unsigned)PKB), "r"(mbar_a)
                         : "memory");
        }
    }

    // ---- hoist radial input loads: latency hides under angular compute ----
    const int  q   = b * 512 + tid;
    const bool vp  = (q < P);
    float rd = 0.0f; int ri = 0, rj = 0;
    if (vp) {
        rd = __ldcs(r_ij + q);
        ri = pidx[q];
        rj = pidx[P + q];
    }

    // ------------------- angular scalars (512 triplets) -------------------
    const long long t = (long long)b * 512 + tid;
    const bool vt = (t < T);

    float cost = 0.f, sint = 0.f, fc2x = 0.f;
    float frad[8];
#pragma unroll
    for (int a = 0; a < 8; a++) frad[a] = 0.f;

    if (vt) {
        const float* v1 = vec12 + 3LL * t;
        const float* v2 = vec12 + 3LL * T + 3LL * t;
        float x1 = __ldcs(v1 + 0), y1 = __ldcs(v1 + 1), z1 = __ldcs(v1 + 2);
        float x2 = __ldcs(v2 + 0), y2 = __ldcs(v2 + 1), z2 = __ldcs(v2 + 2);

        float d11 = fmaf(x1, x1, fmaf(y1, y1, z1 * z1));
        float d22 = fmaf(x2, x2, fmaf(y2, y2, z2 * z2));
        float d12 = fmaf(x1, x2, fmaf(y1, y2, z1 * z2));

        float rs1 = rsqrtf(d11);
        float rs2 = rsqrtf(d22);
        float d1  = d11 * rs1;
        float d2  = d22 * rs2;

        cost = 0.95f * d12 * rs1 * rs2;                 // |cost| <= 0.95
        sint = sqrtf(fmaxf(1.0f - cost * cost, 0.0f));  // theta in [0,pi]

        float fc1 = (d1 <= 3.5f) ? (0.5f * __cosf((PI_F / 3.5f) * d1) + 0.5f) : 0.0f;
        float fc2 = (d2 <= 3.5f) ? (0.5f * __cosf((PI_F / 3.5f) * d2) + 0.5f) : 0.0f;
        fc2x = 2.0f * fc1 * fc2;

        float u = 0.5f * (d1 + d2);
#pragma unroll
        for (int a = 0; a < 8; a++) {
            float dd = u - (0.8f + 0.3375f * (float)a);   // ShfA[a]
            frad[a] = __expf(-12.5f * dd * dd);
        }
    }

    // -------- 4 staging passes: outputs generated inside the pass ---------
    const float CZ[4] = { 0.9238795325f,  0.3826834324f, -0.3826834324f, -0.9238795325f };
    const float SZ[4] = { 0.3826834324f,  0.9238795325f,  0.9238795325f,  0.3826834324f };
    const long long limit = (long long)T * 32;

#pragma unroll
    for (int pass = 0; pass < 4; pass++) {
        if ((tid >> 7) == pass) {
            int r = tid & 127;
#pragma unroll
            for (int z = 0; z < 4; z++) {
                float xz = 0.5f * (1.0f + cost * CZ[z] + sint * SZ[z]);   // in [0,1]
                float fang = (xz > 0.0f) ? __powf(xz, 14.1f) : 0.0f;
                fang *= fc2x;
                float4 a0 = make_float4(fang * frad[0], fang * frad[1],
                                        fang * frad[2], fang * frad[3]);
                float4 a1 = make_float4(fang * frad[4], fang * frad[5],
                                        fang * frad[6], fang * frad[7]);
                *reinterpret_cast<float4*>(&sf[r * 36 + z * 8])     = a0;
                *reinterpret_cast<float4*>(&sf[r * 36 + z * 8 + 4]) = a1;
            }
        }
        __syncthreads();

        // flush: all 512 threads, fully coalesced float4, evict-first
        const long long base = ((long long)b * 512 + pass * 128) * 32;
        if (base < limit) {
            float4* outv = reinterpret_cast<float4*>(ang + base);
#pragma unroll
            for (int it = 0; it < 2; it++) {
                int jj = tid + it * 512;
                if (base + (long long)jj * 4 < limit) {
                    int qr = jj >> 3;
                    int k  = (jj & 7) << 2;
                    __stcs(&outv[jj], *reinterpret_cast<const float4*>(&sf[qr * 36 + k]));
                }
            }
        }
        __syncthreads();
    }

    // ---------------------- wait for species table ------------------------
    if (use_table) {
        unsigned done;
        do {
            asm volatile("{\n\t.reg .pred p;\n\t"
                         "mbarrier.try_wait.parity.shared.b64 p, [%1], 0;\n\t"
                         "selp.b32 %0, 1, 0, p;\n\t}"
                         : "=r"(done) : "r"(mbar_a) : "memory");
        } while (!done);
    }

    // ------------- radial (512 pairs, Gaussian-window culled) -------------
    if (vp) {
        int si, sj;
        if (use_table) {
            si = (spk[ri >> 3] >> ((ri & 7) * 4)) & 7;
            sj = (spk[rj >> 3] >> ((rj & 7) * 4)) & 7;
        } else {
            si = an[ri];
            sj = an[rj];
        }
        float d  = rd;
        float fc = (d <= 5.1f) ? (0.5f * __cosf((PI_F / 5.1f) * d) + 0.5f) : 0.0f;

        // shell coordinate; significant shells: |d - mu_k| < 0.85A
        float s = (d - 0.8f) * 1.8604651f;            // 1/0.5375
        int klo = (int)ceilf(s - 1.582f);
        int khi = (int)floorf(s + 1.582f);
        klo = (klo < 0) ? 0 : ((klo > 7) ? 7 : klo);
        khi = (khi > 7) ? 7 : ((khi < 0) ? 0 : khi);
        int hlo = klo >> 2;
        int hhi = khi >> 2;

        float* rowA = aev + (long long)(ri * 7 + sj) * 8;
        float* rowB = aev + (long long)(rj * 7 + si) * 8;

        for (int h = hlo; h <= hhi; h++) {
            float4 g = radial_half4(d, 0.8f + 2.15f * (float)h, fc);
            atomicAdd(reinterpret_cast<float4*>(rowA + 4 * h), g);
            atomicAdd(reinterpret_cast<float4*>(rowB + 4 * h), g);
        }
    }
}

// ---------------------------------------------------------------------------
// Inputs (metadata order): r_ij f32[P], pair_indices i32[2,P],
// atomic_numbers i32[N_ATOMS], vec12 f32[2,T,3].
// Output: aev f32[N_ATOMS*7, 8] followed by ang f32[T, 32].
// ---------------------------------------------------------------------------
extern "C" void kernel_launch(void* const* d_in, const int* in_sizes, int n_in,
                              void* d_out, int out_size)
{
    const float* r_ij  = (const float*)d_in[0];
    const int*   pidx  = (const int*)  d_in[1];
    const int*   an    = (const int*)  d_in[2];
    const float* vec12 = (const float*)d_in[3];

    const int P = in_sizes[0];
    const int T = in_sizes[3] / 6;
    const int N = in_sizes[2];
    const long long aev_elems = (long long)N * 7 * 8;

    float* aev = (float*)d_out;
    float* ang = aev + aev_elems;

    const int PKW = (N + 7) / 8;                      // packed words
    int PKB = ((PKW * 4) + 15) & ~15;                 // bulk bytes (16B multiple)
    if (PKB > 25088) PKB = 0;                         // table too big -> global gathers

    const int A5 = (T + 511) / 512;                   // angular tiles of 512
    const int R5 = (P + 511) / 512;                   // radial tiles of 512
    const int G  = (A5 > R5) ? A5 : R5;

    // zero aev + pack species (prep also covers table padding words)
    ani_prep_kernel<<<2048, 256>>>(an, N, (PKB > 0) ? (PKB / 4) : 0,
                                   (float4*)aev, aev_elems / 4);

    ani_fused_kernel<<<G, 512>>>(r_ij, pidx, an, vec12, aev, ang, P, T, PKB);
}

// round 13
// speedup vs baseline: 1.5232x; 1.0559x over previous
#include <cuda_runtime.h>
#include <cstdint>

#define PI_F 3.14159265358979323846f

// Packed 4-bit species table (up to 131072 atoms)
__device__ __align__(16) unsigned g_pk[16384];

// ---------------------------------------------------------------------------
// Prep kernel: zero aev AND pack atomic_numbers into 4-bit nibbles.
// ---------------------------------------------------------------------------
__global__ void ani_prep_kernel(const int* __restrict__ an, int N, int PKW,
                                float4* __restrict__ aevv, long long aev_v4)
{
    long long t = (long long)blockIdx.x * blockDim.x + threadIdx.x;
    const float4 z = make_float4(0.f, 0.f, 0.f, 0.f);
    for (long long v = t; v < aev_v4; v += (long long)gridDim.x * blockDim.x)
        aevv[v] = z;
    if (t < PKW) {
        int base = (int)t << 3;
        unsigned v = 0;
#pragma unroll
        for (int k = 0; k < 8; k++) {
            int a = base + k;
            unsigned s = (a < N) ? (unsigned)an[a] : 0u;
            v |= (s & 15u) << (k * 4);
        }
        g_pk[t] = v;
    }
}

__device__ __forceinline__ float4 radial_half4(float d, float base_k, float fc)
{
    float a0 = d - base_k;
    float a1 = d - (base_k + 0.5375f);
    float a2 = d - (base_k + 1.075f);
    float a3 = d - (base_k + 1.6125f);
    return make_float4(0.25f * __expf(-19.7f * a0 * a0) * fc,
                       0.25f * __expf(-19.7f * a1 * a1) * fc,
                       0.25f * __expf(-19.7f * a2 * a2) * fc,
                       0.25f * __expf(-19.7f * a3 * a3) * fc);
}

// ---------------------------------------------------------------------------
// Fused kernel, 384 threads/block, 5 blocks/SM (~94% occ):
//   smem = 25KB species table (cp.async.bulk) + 18.4KB stage (128 rows),
//   reused in 3 staging passes.
//   Radial: Gaussian-window culling, |d - mu_k| < 0.70A significant
//   -> ~78% of pairs touch ONE aligned float4 half (2 atomics not 4).
// ---------------------------------------------------------------------------
__global__ __launch_bounds__(384, 5)
void ani_fused_kernel(const float* __restrict__ r_ij,
                      const int*   __restrict__ pidx,
                      const int*   __restrict__ an,
                      const float* __restrict__ vec12,
                      float*       __restrict__ aev,
                      float*       __restrict__ ang,
                      int P, int T, int PKB /*bulk bytes, 0 = no table*/)
{
    __shared__ __align__(128) unsigned spk[6272];      // 25088B table
    __shared__ __align__(16)  float    sf[128 * 36];   // 18432B stage (128 rows)
    __shared__ __align__(8)   unsigned long long mbar;

    const int tid = threadIdx.x;
    const int b   = blockIdx.x;
    const bool use_table = (PKB > 0);

    uint32_t mbar_a = (uint32_t)__cvta_generic_to_shared(&mbar);

    if (use_table) {
        if (tid == 0) {
            asm volatile("mbarrier.init.shared.b64 [%0], 1;" :: "r"(mbar_a) : "memory");
            asm volatile("fence.proxy.async.shared::cta;" ::: "memory");
        }
        __syncthreads();
        if (tid == 0) {
            uint32_t dst = (uint32_t)__cvta_generic_to_shared(spk);
            asm volatile("mbarrier.arrive.expect_tx.shared.b64 _, [%0], %1;"
                         :: "r"(mbar_a), "r"((unsigned)PKB) : "memory");
            asm volatile("cp.async.bulk.shared::cluster.global.mbarrier::complete_tx::bytes "
                         "[%0], [%1], %2, [%3];"
                         :: "r"(dst), "l"((const void*)g_pk), "r"((unsigned)PKB), "r"(mbar_a)
                         : "memory");
        }
    }

    // ---- hoist radial input loads: latency hides under angular compute ----
    const int  q   = b * 384 + tid;
    const bool vp  = (q < P);
    float rd = 0.0f; int ri = 0, rj = 0;
    if (vp) {
        rd = __ldcs(r_ij + q);
        ri = pidx[q];
        rj = pidx[P + q];
    }

    // ------------------- angular scalars (384 triplets) -------------------
    const long long t = (long long)b * 384 + tid;
    const bool vt = (t < T);

    float cost = 0.f, sint = 0.f, fc2x = 0.f;
    float frad[8];
#pragma unroll
    for (int a = 0; a < 8; a++) frad[a] = 0.f;

    if (vt) {
        const float* v1 = vec12 + 3LL * t;
        const float* v2 = vec12 + 3LL * T + 3LL * t;
        float x1 = __ldcs(v1 + 0), y1 = __ldcs(v1 + 1), z1 = __ldcs(v1 + 2);
        float x2 = __ldcs(v2 + 0), y2 = __ldcs(v2 + 1), z2 = __ldcs(v2 + 2);

        float d11 = fmaf(x1, x1, fmaf(y1, y1, z1 * z1));
        float d22 = fmaf(x2, x2, fmaf(y2, y2, z2 * z2));
        float d12 = fmaf(x1, x2, fmaf(y1, y2, z1 * z2));

        float rs1 = rsqrtf(d11);
        float rs2 = rsqrtf(d22);
        float d1  = d11 * rs1;
        float d2  = d22 * rs2;

        cost = 0.95f * d12 * rs1 * rs2;                 // |cost| <= 0.95
        sint = sqrtf(fmaxf(1.0f - cost * cost, 0.0f));  // theta in [0,pi]

        float fc1 = (d1 <= 3.5f) ? (0.5f * __cosf((PI_F / 3.5f) * d1) + 0.5f) : 0.0f;
        float fc2 = (d2 <= 3.5f) ? (0.5f * __cosf((PI_F / 3.5f) * d2) + 0.5f) : 0.0f;
        fc2x = 2.0f * fc1 * fc2;

        float u = 0.5f * (d1 + d2);
#pragma unroll
        for (int a = 0; a < 8; a++) {
            float dd = u - (0.8f + 0.3375f * (float)a);   // ShfA[a]
            frad[a] = __expf(-12.5f * dd * dd);
        }
    }

    // -------- 3 staging passes: outputs generated inside the pass ---------
    const float CZ[4] = { 0.9238795325f,  0.3826834324f, -0.3826834324f, -0.9238795325f };
    const float SZ[4] = { 0.3826834324f,  0.9238795325f,  0.9238795325f,  0.3826834324f };
    const long long limit = (long long)T * 32;

#pragma unroll
    for (int pass = 0; pass < 3; pass++) {
        if ((tid >> 7) == pass) {
            int r = tid & 127;
#pragma unroll
            for (int z = 0; z < 4; z++) {
                float xz = 0.5f * (1.0f + cost * CZ[z] + sint * SZ[z]);   // in [0,1]
                float fang = (xz > 0.0f) ? __powf(xz, 14.1f) : 0.0f;
                fang *= fc2x;
                float4 a0 = make_float4(fang * frad[0], fang * frad[1],
                                        fang * frad[2], fang * frad[3]);
                float4 a1 = make_float4(fang * frad[4], fang * frad[5],
                                        fang * frad[6], fang * frad[7]);
                *reinterpret_cast<float4*>(&sf[r * 36 + z * 8])     = a0;
                *reinterpret_cast<float4*>(&sf[r * 36 + z * 8 + 4]) = a1;
            }
        }
        __syncthreads();

        // flush: all 384 threads, fully coalesced float4, evict-first
        const long long base = ((long long)b * 384 + pass * 128) * 32;
        if (base < limit) {
            float4* outv = reinterpret_cast<float4*>(ang + base);
#pragma unroll
            for (int it = 0; it < 3; it++) {
                int jj = tid + it * 384;
                if (jj < 1024 && base + (long long)jj * 4 < limit) {
                    int qr = jj >> 3;
                    int k  = (jj & 7) << 2;
                    __stcs(&outv[jj], *reinterpret_cast<const float4*>(&sf[qr * 36 + k]));
                }
            }
        }
        __syncthreads();
    }

    // ---------------------- wait for species table ------------------------
    if (use_table) {
        unsigned done;
        do {
            asm volatile("{\n\t.reg .pred p;\n\t"
                         "mbarrier.try_wait.parity.shared.b64 p, [%1], 0;\n\t"
                         "selp.b32 %0, 1, 0, p;\n\t}"
                         : "=r"(done) : "r"(mbar_a) : "memory");
        } while (!done);
    }

    // ------------- radial (384 pairs, Gaussian-window culled) -------------
    if (vp) {
        int si, sj;
        if (use_table) {
            si = (spk[ri >> 3] >> ((ri & 7) * 4)) & 7;
            sj = (spk[rj >> 3] >> ((rj & 7) * 4)) & 7;
        } else {
            si = an[ri];
            sj = an[rj];
        }
        float d  = rd;
        float fc = (d <= 5.1f) ? (0.5f * __cosf((PI_F / 5.1f) * d) + 0.5f) : 0.0f;

        // shell coordinate; significant shells: |d - mu_k| < 0.70A (1.302 shells)
        float s = (d - 0.8f) * 1.8604651f;            // 1/0.5375
        int klo = (int)ceilf(s - 1.302f);
        int khi = (int)floorf(s + 1.302f);
        klo = (klo < 0) ? 0 : ((klo > 7) ? 7 : klo);
        khi = (khi > 7) ? 7 : ((khi < 0) ? 0 : khi);
        int hlo = klo >> 2;
        int hhi = khi >> 2;

        float* rowA = aev + (long long)(ri * 7 + sj) * 8;
        float* rowB = aev + (long long)(rj * 7 + si) * 8;

        for (int h = hlo; h <= hhi; h++) {
            float4 g = radial_half4(d, 0.8f + 2.15f * (float)h, fc);
            atomicAdd(reinterpret_cast<float4*>(rowA + 4 * h), g);
            atomicAdd(reinterpret_cast<float4*>(rowB + 4 * h), g);
        }
    }
}

// ---------------------------------------------------------------------------
// Inputs (metadata order): r_ij f32[P], pair_indices i32[2,P],
// atomic_numbers i32[N_ATOMS], vec12 f32[2,T,3].
// Output: aev f32[N_ATOMS*7, 8] followed by ang f32[T, 32].
// ---------------------------------------------------------------------------
extern "C" void kernel_launch(void* const* d_in, const int* in_sizes, int n_in,
                              void* d_out, int out_size)
{
    const float* r_ij  = (const float*)d_in[0];
    const int*   pidx  = (const int*)  d_in[1];
    const int*   an    = (const int*)  d_in[2];
    const float* vec12 = (const float*)d_in[3];

    const int P = in_sizes[0];
    const int T = in_sizes[3] / 6;
    const int N = in_sizes[2];
    const long long aev_elems = (long long)N * 7 * 8;

    float* aev = (float*)d_out;
    float* ang = aev + aev_elems;

    const int PKW = (N + 7) / 8;                      // packed words
    int PKB = ((PKW * 4) + 15) & ~15;                 // bulk bytes (16B multiple)
    if (PKB > 25088) PKB = 0;                         // table too big -> global gathers

    const int A3 = (T + 383) / 384;                   // angular tiles of 384
    const int R3 = (P + 383) / 384;                   // radial tiles of 384
    const int G  = (A3 > R3) ? A3 : R3;

    // zero aev + pack species (prep also covers table padding words)
    ani_prep_kernel<<<2048, 256>>>(an, N, (PKB > 0) ? (PKB / 4) : 0,
                                   (float4*)aev, aev_elems / 4);

    ani_fused_kernel<<<G, 384>>>(r_ij, pidx, an, vec12, aev, ang, P, T, PKB);
}

// round 14
// speedup vs baseline: 1.5249x; 1.0011x over previous
#include <cuda_runtime.h>
#include <cstdint>

#define PI_F 3.14159265358979323846f

// Packed 4-bit species table (up to 131072 atoms)
__device__ __align__(16) unsigned g_pk[16384];

// ---------------------------------------------------------------------------
// Prep kernel: zero aev AND pack atomic_numbers into 4-bit nibbles.
// ---------------------------------------------------------------------------
__global__ void ani_prep_kernel(const int* __restrict__ an, int N, int PKW,
                                float4* __restrict__ aevv, long long aev_v4)
{
    long long t = (long long)blockIdx.x * blockDim.x + threadIdx.x;
    const float4 z = make_float4(0.f, 0.f, 0.f, 0.f);
    for (long long v = t; v < aev_v4; v += (long long)gridDim.x * blockDim.x)
        aevv[v] = z;
    if (t < PKW) {
        int base = (int)t << 3;
        unsigned v = 0;
#pragma unroll
        for (int k = 0; k < 8; k++) {
            int a = base + k;
            unsigned s = (a < N) ? (unsigned)an[a] : 0u;
            v |= (s & 15u) << (k * 4);
        }
        g_pk[t] = v;
    }
}

__device__ __forceinline__ float4 radial_half4(float d, float base_k, float fc)
{
    float a0 = d - base_k;
    float a1 = d - (base_k + 0.5375f);
    float a2 = d - (base_k + 1.075f);
    float a3 = d - (base_k + 1.6125f);
    return make_float4(0.25f * __expf(-19.7f * a0 * a0) * fc,
                       0.25f * __expf(-19.7f * a1 * a1) * fc,
                       0.25f * __expf(-19.7f * a2 * a2) * fc,
                       0.25f * __expf(-19.7f * a3 * a3) * fc);
}

// ---------------------------------------------------------------------------
// Fused kernel, 384 threads/block, 5 blocks/SM (~94% occ):
//   smem = 25KB species table (cp.async.bulk) + 18.4KB stage buffer.
//   NEW: vec12 is ALSO bulk-loaded into the stage buffer (idle until after
//   compute) -> the 6 scattered scalar LDG per triplet (~12 sectors each,
//   ~24K cyc/SM of L1 wavefronts) disappear; reads become conflict-free LDS.
//   Radial: Gaussian-window culling (|d-mu| < 0.70A), 2 atomics for ~78%
//   of pairs.
// ---------------------------------------------------------------------------
__global__ __launch_bounds__(384, 5)
void ani_fused_kernel(const float* __restrict__ r_ij,
                      const int*   __restrict__ pidx,
                      const int*   __restrict__ an,
                      const float* __restrict__ vec12,
                      float*       __restrict__ aev,
                      float*       __restrict__ ang,
                      int P, int T, int PKB /*bulk bytes, 0 = no table*/)
{
    __shared__ __align__(128) unsigned spk[6272];      // 25088B table
    __shared__ __align__(128) float    sf[128 * 36];   // 18432B stage / vec12 tile
    __shared__ __align__(8)   unsigned long long mbar_tab;
    __shared__ __align__(8)   unsigned long long mbar_vec;

    const int tid = threadIdx.x;
    const int b   = blockIdx.x;
    const bool use_table = (PKB > 0);

    uint32_t mbtab_a = (uint32_t)__cvta_generic_to_shared(&mbar_tab);
    uint32_t mbvec_a = (uint32_t)__cvta_generic_to_shared(&mbar_vec);

    // fast path: full tile and v2 section 16B-aligned
    const bool fastvec = (((long long)b + 1) * 384 <= (long long)T) && ((T & 3) == 0);

    if (tid == 0) {
        if (use_table)
            asm volatile("mbarrier.init.shared.b64 [%0], 1;" :: "r"(mbtab_a) : "memory");
        if (fastvec)
            asm volatile("mbarrier.init.shared.b64 [%0], 1;" :: "r"(mbvec_a) : "memory");
        asm volatile("fence.proxy.async.shared::cta;" ::: "memory");
    }
    __syncthreads();

    if (tid == 0) {
        if (use_table) {
            uint32_t dst = (uint32_t)__cvta_generic_to_shared(spk);
            asm volatile("mbarrier.arrive.expect_tx.shared.b64 _, [%0], %1;"
                         :: "r"(mbtab_a), "r"((unsigned)PKB) : "memory");
            asm volatile("cp.async.bulk.shared::cluster.global.mbarrier::complete_tx::bytes "
                         "[%0], [%1], %2, [%3];"
                         :: "r"(dst), "l"((const void*)g_pk), "r"((unsigned)PKB), "r"(mbtab_a)
                         : "memory");
        }
        if (fastvec) {
            uint32_t dst = (uint32_t)__cvta_generic_to_shared(sf);
            const float* v1g = vec12 + 3LL * b * 384;
            const float* v2g = vec12 + 3LL * T + 3LL * b * 384;
            asm volatile("mbarrier.arrive.expect_tx.shared.b64 _, [%0], %1;"
                         :: "r"(mbvec_a), "r"(9216u) : "memory");
            asm volatile("cp.async.bulk.shared::cluster.global.mbarrier::complete_tx::bytes "
                         "[%0], [%1], %2, [%3];"
                         :: "r"(dst), "l"((const void*)v1g), "r"(4608u), "r"(mbvec_a)
                         : "memory");
            asm volatile("cp.async.bulk.shared::cluster.global.mbarrier::complete_tx::bytes "
                         "[%0], [%1], %2, [%3];"
                         :: "r"(dst + 4608u), "l"((const void*)v2g), "r"(9216u - 4608u), "r"(mbvec_a)
                         : "memory");
        }
    }

    // ---- hoist radial input loads: latency hides under angular compute ----
    const int  q   = b * 384 + tid;
    const bool vp  = (q < P);
    float rd = 0.0f; int ri = 0, rj = 0;
    if (vp) {
        rd = __ldcs(r_ij + q);
        ri = pidx[q];
        rj = pidx[P + q];
    }

    // ------------------- angular scalars (384 triplets) -------------------
    const long long t = (long long)b * 384 + tid;
    const bool vt = (t < T);

    float x1 = 0.f, y1 = 0.f, z1 = 0.f, x2 = 0.f, y2 = 0.f, z2 = 0.f;

    if (fastvec) {
        unsigned done;
        do {
            asm volatile("{\n\t.reg .pred p;\n\t"
                         "mbarrier.try_wait.parity.shared.b64 p, [%1], 0;\n\t"
                         "selp.b32 %0, 1, 0, p;\n\t}"
                         : "=r"(done) : "r"(mbvec_a) : "memory");
        } while (!done);
        x1 = sf[3 * tid];        y1 = sf[3 * tid + 1];        z1 = sf[3 * tid + 2];
        x2 = sf[1152 + 3 * tid]; y2 = sf[1152 + 3 * tid + 1]; z2 = sf[1152 + 3 * tid + 2];
    } else if (vt) {
        const float* v1 = vec12 + 3LL * t;
        const float* v2 = vec12 + 3LL * T + 3LL * t;
        x1 = __ldcs(v1 + 0); y1 = __ldcs(v1 + 1); z1 = __ldcs(v1 + 2);
        x2 = __ldcs(v2 + 0); y2 = __ldcs(v2 + 1); z2 = __ldcs(v2 + 2);
    }

    float cost = 0.f, sint = 0.f, fc2x = 0.f;
    float frad[8];
#pragma unroll
    for (int a = 0; a < 8; a++) frad[a] = 0.f;

    if (vt) {
        float d11 = fmaf(x1, x1, fmaf(y1, y1, z1 * z1));
        float d22 = fmaf(x2, x2, fmaf(y2, y2, z2 * z2));
        float d12 = fmaf(x1, x2, fmaf(y1, y2, z1 * z2));

        float rs1 = rsqrtf(d11);
        float rs2 = rsqrtf(d22);
        float d1  = d11 * rs1;
        float d2  = d22 * rs2;

        cost = 0.95f * d12 * rs1 * rs2;                 // |cost| <= 0.95
        sint = sqrtf(fmaxf(1.0f - cost * cost, 0.0f));  // theta in [0,pi]

        float fc1 = (d1 <= 3.5f) ? (0.5f * __cosf((PI_F / 3.5f) * d1) + 0.5f) : 0.0f;
        float fc2 = (d2 <= 3.5f) ? (0.5f * __cosf((PI_F / 3.5f) * d2) + 0.5f) : 0.0f;
        fc2x = 2.0f * fc1 * fc2;

        float u = 0.5f * (d1 + d2);
#pragma unroll
        for (int a = 0; a < 8; a++) {
            float dd = u - (0.8f + 0.3375f * (float)a);   // ShfA[a]
            frad[a] = __expf(-12.5f * dd * dd);
        }
    }

    // all LDS reads of sf done before it is reused as the staging buffer
    __syncthreads();

    // -------- 3 staging passes: outputs generated inside the pass ---------
    const float CZ[4] = { 0.9238795325f,  0.3826834324f, -0.3826834324f, -0.9238795325f };
    const float SZ[4] = { 0.3826834324f,  0.9238795325f,  0.9238795325f,  0.3826834324f };
    const long long limit = (long long)T * 32;

#pragma unroll
    for (int pass = 0; pass < 3; pass++) {
        if ((tid >> 7) == pass) {
            int r = tid & 127;
#pragma unroll
            for (int z = 0; z < 4; z++) {
                float xz = 0.5f * (1.0f + cost * CZ[z] + sint * SZ[z]);   // in [0,1]
                float fang = (xz > 0.0f) ? __powf(xz, 14.1f) : 0.0f;
                fang *= fc2x;
                float4 a0 = make_float4(fang * frad[0], fang * frad[1],
                                        fang * frad[2], fang * frad[3]);
                float4 a1 = make_float4(fang * frad[4], fang * frad[5],
                                        fang * frad[6], fang * frad[7]);
                *reinterpret_cast<float4*>(&sf[r * 36 + z * 8])     = a0;
                *reinterpret_cast<float4*>(&sf[r * 36 + z * 8 + 4]) = a1;
            }
        }
        __syncthreads();

        // flush: all 384 threads, fully coalesced float4, evict-first
        const long long base = ((long long)b * 384 + pass * 128) * 32;
        if (base < limit) {
            float4* outv = reinterpret_cast<float4*>(ang + base);
#pragma unroll
            for (int it = 0; it < 3; it++) {
                int jj = tid + it * 384;
                if (jj < 1024 && base + (long long)jj * 4 < limit) {
                    int qr = jj >> 3;
                    int k  = (jj & 7) << 2;
                    __stcs(&outv[jj], *reinterpret_cast<const float4*>(&sf[qr * 36 + k]));
                }
            }
        }
        __syncthreads();
    }

    // ---------------------- wait for species table ------------------------
    if (use_table) {
        unsigned done;
        do {
            asm volatile("{\n\t.reg .pred p;\n\t"
                         "mbarrier.try_wait.parity.shared.b64 p, [%1], 0;\n\t"
                         "selp.b32 %0, 1, 0, p;\n\t}"
                         : "=r"(done) : "r"(mbtab_a) : "memory");
        } while (!done);
    }

    // ------------- radial (384 pairs, Gaussian-window culled) -------------
    if (vp) {
        int si, sj;
        if (use_table) {
            si = (spk[ri >> 3] >> ((ri & 7) * 4)) & 7;
            sj = (spk[rj >> 3] >> ((rj & 7) * 4)) & 7;
        } else {
            si = an[ri];
            sj = an[rj];
        }
        float d  = rd;
        float fc = (d <= 5.1f) ? (0.5f * __cosf((PI_F / 5.1f) * d) + 0.5f) : 0.0f;

        // shell coordinate; significant shells: |d - mu_k| < 0.70A (1.302 shells)
        float s = (d - 0.8f) * 1.8604651f;            // 1/0.5375
        int klo = (int)ceilf(s - 1.302f);
        int khi = (int)floorf(s + 1.302f);
        klo = (klo < 0) ? 0 : ((klo > 7) ? 7 : klo);
        khi = (khi > 7) ? 7 : ((khi < 0) ? 0 : khi);
        int hlo = klo >> 2;
        int hhi = khi >> 2;

        float* rowA = aev + (long long)(ri * 7 + sj) * 8;
        float* rowB = aev + (long long)(rj * 7 + si) * 8;

        for (int h = hlo; h <= hhi; h++) {
            float4 g = radial_half4(d, 0.8f + 2.15f * (float)h, fc);
            atomicAdd(reinterpret_cast<float4*>(rowA + 4 * h), g);
            atomicAdd(reinterpret_cast<float4*>(rowB + 4 * h), g);
        }
    }
}

// ---------------------------------------------------------------------------
// Inputs (metadata order): r_ij f32[P], pair_indices i32[2,P],
// atomic_numbers i32[N_ATOMS], vec12 f32[2,T,3].
// Output: aev f32[N_ATOMS*7, 8] followed by ang f32[T, 32].
// ---------------------------------------------------------------------------
extern "C" void kernel_launch(void* const* d_in, const int* in_sizes, int n_in,
                              void* d_out, int out_size)
{
    const float* r_ij  = (const float*)d_in[0];
    const int*   pidx  = (const int*)  d_in[1];
    const int*   an    = (const int*)  d_in[2];
    const float* vec12 = (const float*)d_in[3];

    const int P = in_sizes[0];
    const int T = in_sizes[3] / 6;
    const int N = in_sizes[2];
    const long long aev_elems = (long long)N * 7 * 8;

    float* aev = (float*)d_out;
    float* ang = aev + aev_elems;

    const int PKW = (N + 7) / 8;                      // packed words
    int PKB = ((PKW * 4) + 15) & ~15;                 // bulk bytes (16B multiple)
    if (PKB > 25088) PKB = 0;                         // table too big -> global gathers

    const int A3 = (T + 383) / 384;                   // angular tiles of 384
    const int R3 = (P + 383) / 384;                   // radial tiles of 384
    const int G  = (A3 > R3) ? A3 : R3;

    // zero aev + pack species (prep also covers table padding words)
    ani_prep_kernel<<<2048, 256>>>(an, N, (PKB > 0) ? (PKB / 4) : 0,
                                   (float4*)aev, aev_elems / 4);

    ani_fused_kernel<<<G, 384>>>(r_ij, pidx, an, vec12, aev, ang, P, T, PKB);
}